// round 7
// baseline (speedup 1.0000x reference)
#include <cuda_runtime.h>
#include <cstdint>

#define B_  2
#define S_  2048
#define D_  1024
#define H_  16
#define DH_ 64
#define M_  (B_*S_)

// Scratch for projected Q/K/V (allocation-free rule: __device__ globals)
__device__ float g_Q[M_*D_];
__device__ float g_K[M_*D_];
__device__ float g_V[M_*D_];

// ---------------------------------------------------------------------------
// Helpers (all family-level PTX: sm_80+/sm_100f — no arch-specific suffixes)
// ---------------------------------------------------------------------------
__device__ __forceinline__ uint32_t smem_u32(const void* p){
    uint32_t a;
    asm("{ .reg .u64 t; cvta.to.shared.u64 t, %1; cvt.u32.u64 %0, t; }"
        : "=r"(a) : "l"(p));
    return a;
}
__device__ __forceinline__ float to_tf32(float x){
    asm("cvt.rna.tf32.f32 %0, %0;" : "+f"(x));
    return x;
}
__device__ __forceinline__ void cp16(uint32_t dst, const void* src){
    asm volatile("cp.async.cg.shared.global [%0], [%1], 16;"
                 :: "r"(dst), "l"(src) : "memory");
}
__device__ __forceinline__ void cp_commit(){
    asm volatile("cp.async.commit_group;" ::: "memory");
}
__device__ __forceinline__ void cp_wait0(){
    asm volatile("cp.async.wait_group 0;" ::: "memory");
}
// m16n8k8 tf32 mma (sm_80+): D = A*B + D
__device__ __forceinline__ void mma_tf32(float* c, const float* a, const float* b){
    asm volatile(
        "mma.sync.aligned.m16n8k8.row.col.f32.tf32.tf32.f32 "
        "{%0,%1,%2,%3}, {%4,%5,%6,%7}, {%8,%9}, {%0,%1,%2,%3};"
        : "+f"(c[0]), "+f"(c[1]), "+f"(c[2]), "+f"(c[3])
        : "r"(__float_as_uint(a[0])), "r"(__float_as_uint(a[1])),
          "r"(__float_as_uint(a[2])), "r"(__float_as_uint(a[3])),
          "r"(__float_as_uint(b[0])), "r"(__float_as_uint(b[1])));
}
// packed fp32x2 helpers (FFMA2: 2x fp32 throughput, PTX-only)
__device__ __forceinline__ unsigned long long pk(float lo, float hi){
    unsigned long long r;
    asm("mov.b64 %0, {%1, %2};" : "=l"(r) : "f"(lo), "f"(hi));
    return r;
}
__device__ __forceinline__ void fma2(unsigned long long& d,
                                     unsigned long long a, unsigned long long b){
    asm("fma.rn.f32x2 %0, %1, %2, %0;" : "+l"(d) : "l"(a), "l"(b));
}
__device__ __forceinline__ void mul2(unsigned long long& d, unsigned long long a){
    asm("mul.rn.f32x2 %0, %0, %1;" : "+l"(d) : "l"(a));
}
__device__ __forceinline__ void unpk(unsigned long long v, float& lo, float& hi){
    asm("mov.b64 {%0, %1}, %2;" : "=f"(lo), "=f"(hi) : "l"(v));
}

// ---------------------------------------------------------------------------
// Projection GEMM via mma.sync tf32: C = A[4096,1024] @ W[1024,1024] + bias
// 128x128 tile, K-chunks of 32, cp.async double-buffered smem.
// 256 thr = 8 warps; warp tile 64x32 (wm=wid>>2 in {0,1}, wn=wid&3 in {0..3}).
// ---------------------------------------------------------------------------
#define AST 36                      // A smem row stride (floats), pad 4
#define BST 136                     // B smem row stride (floats), pad 8
#define PA_FLOATS (128*AST)         // 4608
#define PB_FLOATS (32*BST)          // 4352
#define PBUF_FLOATS (PA_FLOATS + PB_FLOATS)
#define PA_BYTES (PA_FLOATS*4)
#define PBUF_BYTES (PBUF_FLOATS*4)
#define PSMEM_TOT (2*PBUF_BYTES)    // 71680

__global__ __launch_bounds__(256, 2)
void proj_mma(const float* __restrict__ Aq, const float* __restrict__ Ak,
              const float* __restrict__ Av,
              const float* __restrict__ Wq, const float* __restrict__ Wk,
              const float* __restrict__ Wv,
              const float* __restrict__ bq, const float* __restrict__ bk,
              const float* __restrict__ bv)
{
    extern __shared__ float sm[];
    const uint32_t smb = smem_u32(sm);
    const int tid  = threadIdx.x;
    const int wid  = tid >> 5;
    const int lane = tid & 31;
    const int wm   = wid >> 2;      // 0..1
    const int wn   = wid & 3;       // 0..3
    const int grp  = lane >> 2;     // 0..7
    const int qd   = lane & 3;      // 0..3

    const int z = blockIdx.z;
    const float* A    = (z == 0) ? Aq : (z == 1) ? Ak : Av;
    const float* W    = (z == 0) ? Wq : (z == 1) ? Wk : Wv;
    const float* bias = (z == 0) ? bq : (z == 1) ? bk : bv;
    float* C          = (z == 0) ? g_Q : (z == 1) ? g_K : g_V;
    const int brow = blockIdx.y * 128;
    const int bcol = blockIdx.x * 128;

    auto cp_chunk = [&](int c, int buf){
        const int k0 = c * 32;
        const uint32_t Ab = smb + buf * PBUF_BYTES;
        const uint32_t Bb = Ab + PA_BYTES;
        #pragma unroll
        for (int it = 0; it < 4; it++) {
            int idx = tid + it * 256;           // 0..1023
            int row = idx >> 3;                 // 0..127
            int k4  = idx & 7;                  // float4 within 32 k
            cp16(Ab + row * (AST*4) + k4 * 16,
                 &A[(size_t)(brow + row) * D_ + k0 + k4 * 4]);
        }
        #pragma unroll
        for (int it = 0; it < 4; it++) {
            int idx = tid + it * 256;
            int kk  = idx >> 5;                 // 0..31
            int n4  = idx & 31;                 // float4 within 128 n
            cp16(Bb + kk * (BST*4) + n4 * 16,
                 &W[(size_t)(k0 + kk) * D_ + bcol + n4 * 4]);
        }
    };

    float acc[4][4][4];
    #pragma unroll
    for (int i = 0; i < 4; i++)
        #pragma unroll
        for (int j = 0; j < 4; j++)
            #pragma unroll
            for (int r = 0; r < 4; r++) acc[i][j][r] = 0.f;

    cp_chunk(0, 0);
    cp_commit();
    cp_wait0();
    __syncthreads();

    for (int c = 0; c < 32; c++) {
        const int buf = c & 1;
        const float* A_s = sm + buf * PBUF_FLOATS;
        const float* B_s = A_s + PA_FLOATS;

        if (c + 1 < 32) { cp_chunk(c + 1, buf ^ 1); cp_commit(); }

        #pragma unroll
        for (int ks = 0; ks < 4; ks++) {
            float a[4][4];
            #pragma unroll
            for (int i = 0; i < 4; i++) {
                const int r0 = wm * 64 + i * 16 + grp;
                const float* Ar = &A_s[r0 * AST + ks * 8 + qd];
                a[i][0] = to_tf32(Ar[0]);
                a[i][1] = to_tf32(Ar[8 * AST]);
                a[i][2] = to_tf32(Ar[4]);
                a[i][3] = to_tf32(Ar[8 * AST + 4]);
            }
            float bf[4][2];
            #pragma unroll
            for (int j = 0; j < 4; j++) {
                const int col = wn * 32 + j * 8 + grp;
                bf[j][0] = to_tf32(B_s[(ks * 8 + qd) * BST + col]);
                bf[j][1] = to_tf32(B_s[(ks * 8 + qd + 4) * BST + col]);
            }
            #pragma unroll
            for (int i = 0; i < 4; i++)
                #pragma unroll
                for (int j = 0; j < 4; j++)
                    mma_tf32(acc[i][j], a[i], bf[j]);
        }

        if (c + 1 < 32) cp_wait0();
        __syncthreads();
    }

    // Epilogue: c0,c1 -> (row, 2q),(row, 2q+1); c2,c3 -> row+8
    #pragma unroll
    for (int j = 0; j < 4; j++) {
        const int c0 = bcol + wn * 32 + j * 8 + qd * 2;
        const float2 bb = *(const float2*)&bias[c0];
        #pragma unroll
        for (int i = 0; i < 4; i++) {
            const int r0 = brow + wm * 64 + i * 16 + grp;
            float2 o0 = make_float2(acc[i][j][0] + bb.x, acc[i][j][1] + bb.y);
            float2 o1 = make_float2(acc[i][j][2] + bb.x, acc[i][j][3] + bb.y);
            *(float2*)&C[(size_t)r0 * D_ + c0]       = o0;
            *(float2*)&C[(size_t)(r0 + 8) * D_ + c0] = o1;
        }
    }
}

// ---------------------------------------------------------------------------
// Flash attention (fp32, f32x2-packed FMAs). One CTA = 128 q-rows of one
// (b,h); loops kv in 64s. 128 threads, 8x8 microtile, XOR-swizzled tiles.
// ---------------------------------------------------------------------------
#define BM  128
#define BN  64
#define ATH 128

#define ASMEM_FLOATS (64*128 + 64*64 + 64*64 + 64*128 + 64)
#define ASMEM_BYTES  (ASMEM_FLOATS * 4)

__global__ __launch_bounds__(ATH, 2)
void flash_attn(const int* __restrict__ mask, float* __restrict__ out)
{
    extern __shared__ float smf[];
    float* Qs   = smf;              // [d][r] swizzled, stride 128
    float* Ks   = Qs + 64*128;      // [d][c] swizzled, stride 64
    float* Vs   = Ks + 64*64;       // [kv][c] natural, stride 64
    float* Ps   = Vs + 64*64;       // [kv][r] swizzled, stride 128
    float* madd = Ps + 64*128;      // [64] additive mask

    const int tid = threadIdx.x;
    const int ty  = tid >> 3;       // 0..15 -> rows
    const int tx  = tid & 7;        // 0..7  -> cols
    const int R   = ty << 3;
    const int C   = tx << 3;
    const int bh  = blockIdx.y;
    const int b   = bh >> 4;        // H_=16
    const int h   = bh & 15;
    const int q0  = blockIdx.x * BM;
    const float scale = 0.03125f;   // 1/sqrt(1024)

    const float* Qb = g_Q + (size_t)b * S_ * D_ + h * DH_;
    const float* Kb = g_K + (size_t)b * S_ * D_ + h * DH_;
    const float* Vb = g_V + (size_t)b * S_ * D_ + h * DH_;

    // Load Q tile [128 x 64] transposed + swizzled
    #pragma unroll
    for (int l = 0; l < 16; l++) {
        int idx = tid + l * ATH;
        int row = idx >> 4;
        int dz  = idx & 15;
        float4 v = *(const float4*)&Qb[(q0 + row) * D_ + (dz << 2)];
        int blk = (((row >> 2) ^ dz) << 2) + (row & 3);
        Qs[(dz*4 + 0)*128 + blk] = v.x;
        Qs[(dz*4 + 1)*128 + blk] = v.y;
        Qs[(dz*4 + 2)*128 + blk] = v.z;
        Qs[(dz*4 + 3)*128 + blk] = v.w;
    }

    float m_i[8], l_i[8];
    unsigned long long o2[8][4];
    #pragma unroll
    for (int i = 0; i < 8; i++) {
        m_i[i] = -1e30f; l_i[i] = 0.f;
        #pragma unroll
        for (int j = 0; j < 4; j++) o2[i][j] = 0ull;
    }

    for (int kv0 = 0; kv0 < S_; kv0 += BN) {
        __syncthreads();   // prior PV reads of Vs/Ps done before overwrite

        // Load K (transposed+swizzled) and V (natural) tiles [64 x 64]
        #pragma unroll
        for (int l = 0; l < 8; l++) {
            int idx = tid + l * ATH;
            int row = idx >> 4;
            int dz  = idx & 15;
            float4 kv4 = *(const float4*)&Kb[(kv0 + row) * D_ + (dz << 2)];
            int blk = (((row >> 2) ^ dz) << 2) + (row & 3);
            Ks[(dz*4 + 0)*64 + blk] = kv4.x;
            Ks[(dz*4 + 1)*64 + blk] = kv4.y;
            Ks[(dz*4 + 2)*64 + blk] = kv4.z;
            Ks[(dz*4 + 3)*64 + blk] = kv4.w;
            float4 vv4 = *(const float4*)&Vb[(kv0 + row) * D_ + (dz << 2)];
            *(float4*)&Vs[row*64 + (dz << 2)] = vv4;
        }
        if (tid < 64)
            madd[tid] = mask[b * S_ + kv0 + tid] ? 0.f : -1e9f;
        __syncthreads();

        // S = Q K^T  (8x8 per thread, f32x2-packed along j)
        unsigned long long s2[8][4];
        #pragma unroll
        for (int i = 0; i < 8; i++)
            #pragma unroll
            for (int j = 0; j < 4; j++) s2[i][j] = 0ull;

        #pragma unroll 8
        for (int d = 0; d < 64; d++) {
            int dz = d >> 2;
            float a[8];
            float4 t;
            t = *(float4*)&Qs[d*128 + (((2*ty  ) ^ dz) << 2)];
            a[0]=t.x; a[1]=t.y; a[2]=t.z; a[3]=t.w;
            t = *(float4*)&Qs[d*128 + (((2*ty+1) ^ dz) << 2)];
            a[4]=t.x; a[5]=t.y; a[6]=t.z; a[7]=t.w;
            float4 tb0 = *(float4*)&Ks[d*64 + (((2*tx  ) ^ dz) << 2)];
            float4 tb1 = *(float4*)&Ks[d*64 + (((2*tx+1) ^ dz) << 2)];
            unsigned long long b2[4];
            b2[0] = pk(tb0.x, tb0.y);
            b2[1] = pk(tb0.z, tb0.w);
            b2[2] = pk(tb1.x, tb1.y);
            b2[3] = pk(tb1.z, tb1.w);
            #pragma unroll
            for (int i = 0; i < 8; i++) {
                unsigned long long ad = pk(a[i], a[i]);
                #pragma unroll
                for (int j = 0; j < 4; j++) fma2(s2[i][j], ad, b2[j]);
            }
        }

        float ma[8];
        #pragma unroll
        for (int j = 0; j < 8; j++) ma[j] = madd[C + j];

        // Online softmax update (row reduction across the 8-lane tx group)
        #pragma unroll
        for (int i = 0; i < 8; i++) {
            float s[8];
            unpk(s2[i][0], s[0], s[1]);
            unpk(s2[i][1], s[2], s[3]);
            unpk(s2[i][2], s[4], s[5]);
            unpk(s2[i][3], s[6], s[7]);
            #pragma unroll
            for (int j = 0; j < 8; j++) s[j] = fmaf(s[j], scale, ma[j]);
            float mx = s[0];
            #pragma unroll
            for (int j = 1; j < 8; j++) mx = fmaxf(mx, s[j]);
            mx = fmaxf(mx, __shfl_xor_sync(0xffffffffu, mx, 1));
            mx = fmaxf(mx, __shfl_xor_sync(0xffffffffu, mx, 2));
            mx = fmaxf(mx, __shfl_xor_sync(0xffffffffu, mx, 4));
            float mn = fmaxf(m_i[i], mx);
            float al = __expf(m_i[i] - mn);
            float rs = 0.f;
            #pragma unroll
            for (int j = 0; j < 8; j++) {
                float p = __expf(s[j] - mn);
                s[j] = p;
                rs += p;
            }
            rs += __shfl_xor_sync(0xffffffffu, rs, 1);
            rs += __shfl_xor_sync(0xffffffffu, rs, 2);
            rs += __shfl_xor_sync(0xffffffffu, rs, 4);
            l_i[i] = l_i[i] * al + rs;
            m_i[i] = mn;
            unsigned long long al2 = pk(al, al);
            #pragma unroll
            for (int j = 0; j < 4; j++) mul2(o2[i][j], al2);
            // store P transposed+swizzled: Ps[kv][r]
            int r = R + i;
            #pragma unroll
            for (int j = 0; j < 8; j++) {
                int kv = C + j;
                Ps[kv*128 + (((r >> 2) ^ (kv >> 2)) << 2) + (r & 3)] = s[j];
            }
        }
        __syncthreads();

        // O += P V  (8x8 per thread, f32x2-packed along j)
        #pragma unroll 8
        for (int kv = 0; kv < 64; kv++) {
            int kz = kv >> 2;
            float p[8];
            float4 t;
            t = *(float4*)&Ps[kv*128 + (((2*ty  ) ^ kz) << 2)];
            p[0]=t.x; p[1]=t.y; p[2]=t.z; p[3]=t.w;
            t = *(float4*)&Ps[kv*128 + (((2*ty+1) ^ kz) << 2)];
            p[4]=t.x; p[5]=t.y; p[6]=t.z; p[7]=t.w;
            float4 tv0 = *(float4*)&Vs[kv*64 + C];
            float4 tv1 = *(float4*)&Vs[kv*64 + C + 4];
            unsigned long long v2[4];
            v2[0] = pk(tv0.x, tv0.y);
            v2[1] = pk(tv0.z, tv0.w);
            v2[2] = pk(tv1.x, tv1.y);
            v2[3] = pk(tv1.z, tv1.w);
            #pragma unroll
            for (int i = 0; i < 8; i++) {
                unsigned long long pd = pk(p[i], p[i]);
                #pragma unroll
                for (int j = 0; j < 4; j++) fma2(o2[i][j], pd, v2[j]);
            }
        }
    }

    // Normalize and write out[b, q0+R+i, h*64 + C + j]
    #pragma unroll
    for (int i = 0; i < 8; i++) {
        float inv = 1.f / l_i[i];
        float o[8];
        unpk(o2[i][0], o[0], o[1]);
        unpk(o2[i][1], o[2], o[3]);
        unpk(o2[i][2], o[4], o[5]);
        unpk(o2[i][3], o[6], o[7]);
        float4 o0 = make_float4(o[0]*inv, o[1]*inv, o[2]*inv, o[3]*inv);
        float4 o1 = make_float4(o[4]*inv, o[5]*inv, o[6]*inv, o[7]*inv);
        size_t base = ((size_t)b * S_ + q0 + R + i) * D_ + h * DH_ + C;
        *(float4*)&out[base]     = o0;
        *(float4*)&out[base + 4] = o1;
    }
}

// ---------------------------------------------------------------------------
extern "C" void kernel_launch(void* const* d_in, const int* in_sizes, int n_in,
                              void* d_out, int out_size)
{
    const float* q    = (const float*)d_in[0];
    const float* k    = (const float*)d_in[1];
    const float* v    = (const float*)d_in[2];
    const int*   mask = (const int*)  d_in[3];
    const float* Wq   = (const float*)d_in[4];
    const float* bq   = (const float*)d_in[5];
    const float* Wk   = (const float*)d_in[6];
    const float* bk   = (const float*)d_in[7];
    const float* Wv   = (const float*)d_in[8];
    const float* bv   = (const float*)d_in[9];
    float* out = (float*)d_out;

    (void)in_sizes; (void)n_in; (void)out_size;

    cudaFuncSetAttribute(proj_mma,
                         cudaFuncAttributeMaxDynamicSharedMemorySize, PSMEM_TOT);
    dim3 g1(D_/128, M_/128, 3);   // 8 x 32 x 3
    proj_mma<<<g1, 256, PSMEM_TOT>>>(q, k, v, Wq, Wk, Wv, bq, bk, bv);

    cudaFuncSetAttribute(flash_attn,
                         cudaFuncAttributeMaxDynamicSharedMemorySize,
                         ASMEM_BYTES);
    dim3 g2(S_/BM, B_*H_);        // 16 x 32
    flash_attn<<<g2, ATH, ASMEM_BYTES>>>(mask, out);
}

// round 8
// speedup vs baseline: 3.8843x; 3.8843x over previous
#include <cuda_runtime.h>
#include <cstdint>

#define B_  2
#define S_  2048
#define D_  1024
#define H_  16
#define DH_ 64
#define M_  (B_*S_)

// Scratch for projected Q/K/V (allocation-free rule: __device__ globals)
__device__ float g_Q[M_*D_];
__device__ float g_K[M_*D_];
__device__ float g_V[M_*D_];

// ---------------------------------------------------------------------------
// Helpers (all family-level PTX: sm_80+/sm_100f — no arch-specific suffixes)
// ---------------------------------------------------------------------------
__device__ __forceinline__ uint32_t smem_u32(const void* p){
    uint32_t a;
    asm("{ .reg .u64 t; cvta.to.shared.u64 t, %1; cvt.u32.u64 %0, t; }"
        : "=r"(a) : "l"(p));
    return a;
}
__device__ __forceinline__ float to_tf32(float x){
    asm("cvt.rna.tf32.f32 %0, %0;" : "+f"(x));
    return x;
}
__device__ __forceinline__ void cp16(uint32_t dst, const void* src){
    asm volatile("cp.async.cg.shared.global [%0], [%1], 16;"
                 :: "r"(dst), "l"(src) : "memory");
}
__device__ __forceinline__ void cp_commit(){
    asm volatile("cp.async.commit_group;" ::: "memory");
}
__device__ __forceinline__ void cp_wait0(){
    asm volatile("cp.async.wait_group 0;" ::: "memory");
}
// m16n8k8 tf32 mma (sm_80+): D = A*B + D
__device__ __forceinline__ void mma_tf32(float* c, const float* a, const float* b){
    asm volatile(
        "mma.sync.aligned.m16n8k8.row.col.f32.tf32.tf32.f32 "
        "{%0,%1,%2,%3}, {%4,%5,%6,%7}, {%8,%9}, {%0,%1,%2,%3};"
        : "+f"(c[0]), "+f"(c[1]), "+f"(c[2]), "+f"(c[3])
        : "r"(__float_as_uint(a[0])), "r"(__float_as_uint(a[1])),
          "r"(__float_as_uint(a[2])), "r"(__float_as_uint(a[3])),
          "r"(__float_as_uint(b[0])), "r"(__float_as_uint(b[1])));
}

// ---------------------------------------------------------------------------
// Projection GEMM via mma.sync tf32 (unchanged from passing R7 version)
// ---------------------------------------------------------------------------
#define AST 36
#define BST 136
#define PA_FLOATS (128*AST)
#define PB_FLOATS (32*BST)
#define PBUF_FLOATS (PA_FLOATS + PB_FLOATS)
#define PA_BYTES (PA_FLOATS*4)
#define PBUF_BYTES (PBUF_FLOATS*4)
#define PSMEM_TOT (2*PBUF_BYTES)

__global__ __launch_bounds__(256, 2)
void proj_mma(const float* __restrict__ Aq, const float* __restrict__ Ak,
              const float* __restrict__ Av,
              const float* __restrict__ Wq, const float* __restrict__ Wk,
              const float* __restrict__ Wv,
              const float* __restrict__ bq, const float* __restrict__ bk,
              const float* __restrict__ bv)
{
    extern __shared__ float sm[];
    const uint32_t smb = smem_u32(sm);
    const int tid  = threadIdx.x;
    const int wid  = tid >> 5;
    const int lane = tid & 31;
    const int wm   = wid >> 2;
    const int wn   = wid & 3;
    const int grp  = lane >> 2;
    const int qd   = lane & 3;

    const int z = blockIdx.z;
    const float* A    = (z == 0) ? Aq : (z == 1) ? Ak : Av;
    const float* W    = (z == 0) ? Wq : (z == 1) ? Wk : Wv;
    const float* bias = (z == 0) ? bq : (z == 1) ? bk : bv;
    float* C          = (z == 0) ? g_Q : (z == 1) ? g_K : g_V;
    const int brow = blockIdx.y * 128;
    const int bcol = blockIdx.x * 128;

    auto cp_chunk = [&](int c, int buf){
        const int k0 = c * 32;
        const uint32_t Ab = smb + buf * PBUF_BYTES;
        const uint32_t Bb = Ab + PA_BYTES;
        #pragma unroll
        for (int it = 0; it < 4; it++) {
            int idx = tid + it * 256;
            int row = idx >> 3;
            int k4  = idx & 7;
            cp16(Ab + row * (AST*4) + k4 * 16,
                 &A[(size_t)(brow + row) * D_ + k0 + k4 * 4]);
        }
        #pragma unroll
        for (int it = 0; it < 4; it++) {
            int idx = tid + it * 256;
            int kk  = idx >> 5;
            int n4  = idx & 31;
            cp16(Bb + kk * (BST*4) + n4 * 16,
                 &W[(size_t)(k0 + kk) * D_ + bcol + n4 * 4]);
        }
    };

    float acc[4][4][4];
    #pragma unroll
    for (int i = 0; i < 4; i++)
        #pragma unroll
        for (int j = 0; j < 4; j++)
            #pragma unroll
            for (int r = 0; r < 4; r++) acc[i][j][r] = 0.f;

    cp_chunk(0, 0);
    cp_commit();
    cp_wait0();
    __syncthreads();

    for (int c = 0; c < 32; c++) {
        const int buf = c & 1;
        const float* A_s = sm + buf * PBUF_FLOATS;
        const float* B_s = A_s + PA_FLOATS;

        if (c + 1 < 32) { cp_chunk(c + 1, buf ^ 1); cp_commit(); }

        #pragma unroll
        for (int ks = 0; ks < 4; ks++) {
            float a[4][4];
            #pragma unroll
            for (int i = 0; i < 4; i++) {
                const int r0 = wm * 64 + i * 16 + grp;
                const float* Ar = &A_s[r0 * AST + ks * 8 + qd];
                a[i][0] = to_tf32(Ar[0]);
                a[i][1] = to_tf32(Ar[8 * AST]);
                a[i][2] = to_tf32(Ar[4]);
                a[i][3] = to_tf32(Ar[8 * AST + 4]);
            }
            float bf[4][2];
            #pragma unroll
            for (int j = 0; j < 4; j++) {
                const int col = wn * 32 + j * 8 + grp;
                bf[j][0] = to_tf32(B_s[(ks * 8 + qd) * BST + col]);
                bf[j][1] = to_tf32(B_s[(ks * 8 + qd + 4) * BST + col]);
            }
            #pragma unroll
            for (int i = 0; i < 4; i++)
                #pragma unroll
                for (int j = 0; j < 4; j++)
                    mma_tf32(acc[i][j], a[i], bf[j]);
        }

        if (c + 1 < 32) cp_wait0();
        __syncthreads();
    }

    #pragma unroll
    for (int j = 0; j < 4; j++) {
        const int c0 = bcol + wn * 32 + j * 8 + qd * 2;
        const float2 bb = *(const float2*)&bias[c0];
        #pragma unroll
        for (int i = 0; i < 4; i++) {
            const int r0 = brow + wm * 64 + i * 16 + grp;
            float2 o0 = make_float2(acc[i][j][0] + bb.x, acc[i][j][1] + bb.y);
            float2 o1 = make_float2(acc[i][j][2] + bb.x, acc[i][j][3] + bb.y);
            *(float2*)&C[(size_t)r0 * D_ + c0]       = o0;
            *(float2*)&C[(size_t)(r0 + 8) * D_ + c0] = o1;
        }
    }
}

// ---------------------------------------------------------------------------
// Flash attention via mma.sync tf32.
// CTA: 128 threads (4 warps), BM=128 q-rows (32/warp), kv tiles of 64.
// Q/K/P pad-stride 68 (banks 4*grp+qd: conflict-free fragment loads),
// V pad-stride 72 (banks 8*qd+grp: conflict-free B-fragment loads).
// ---------------------------------------------------------------------------
#define QST 68
#define KST 68
#define VST 72
#define PST 68
#define FA_SMEM_FLOATS (128*QST + 64*KST + 64*VST + 128*PST + 64)
#define FA_SMEM_BYTES  (FA_SMEM_FLOATS * 4)

__global__ __launch_bounds__(128, 2)
void flash_attn_mma(const int* __restrict__ mask, float* __restrict__ out)
{
    extern __shared__ float smf[];
    float* Qs   = smf;                  // [128][QST] tf32
    float* Ks   = Qs + 128*QST;         // [64][KST]  tf32
    float* Vs   = Ks + 64*KST;          // [64][VST]  tf32
    float* Ps   = Vs + 64*VST;          // [128][PST] tf32 (per-warp rows)
    float* madd = Ps + 128*PST;         // [64] additive mask

    const int tid  = threadIdx.x;
    const int w    = tid >> 5;          // 0..3 -> q rows [w*32, w*32+32)
    const int lane = tid & 31;
    const int grp  = lane >> 2;         // 0..7
    const int qd   = lane & 3;          // 0..3
    const int bh   = blockIdx.y;
    const int b    = bh >> 4;
    const int h    = bh & 15;
    const int q0   = blockIdx.x * 128;
    const float scale = 0.03125f;       // 1/sqrt(1024)

    const float* Qb = g_Q + (size_t)b * S_ * D_ + h * DH_;
    const float* Kb = g_K + (size_t)b * S_ * D_ + h * DH_;
    const float* Vb = g_V + (size_t)b * S_ * D_ + h * DH_;

    // Load Q tile [128 x 64] -> tf32 smem (stride 68, float4-aligned)
    #pragma unroll
    for (int l = 0; l < 16; l++) {
        int idx = tid + l * 128;        // 0..2047 float4s
        int row = idx >> 4;
        int c4  = idx & 15;
        float4 v = *(const float4*)&Qb[(size_t)(q0 + row) * D_ + c4 * 4];
        v.x = to_tf32(v.x); v.y = to_tf32(v.y);
        v.z = to_tf32(v.z); v.w = to_tf32(v.w);
        *(float4*)&Qs[row * QST + c4 * 4] = v;
    }

    float o[2][8][4];
    float m_i[2][2], l_i[2][2];
    #pragma unroll
    for (int mi = 0; mi < 2; mi++) {
        m_i[mi][0] = -1e30f; m_i[mi][1] = -1e30f;
        l_i[mi][0] = 0.f;    l_i[mi][1] = 0.f;
        #pragma unroll
        for (int nt = 0; nt < 8; nt++)
            #pragma unroll
            for (int r = 0; r < 4; r++) o[mi][nt][r] = 0.f;
    }

    for (int kv0 = 0; kv0 < S_; kv0 += 64) {
        __syncthreads();    // prior iter's K/V fragment reads complete

        // Load K [64x64] (stride 68) and V [64x64] (stride 72), tf32
        #pragma unroll
        for (int l = 0; l < 8; l++) {
            int idx = tid + l * 128;    // 0..1023 float4s
            int row = idx >> 4;
            int c4  = idx & 15;
            float4 kv4 = *(const float4*)&Kb[(size_t)(kv0 + row) * D_ + c4 * 4];
            kv4.x = to_tf32(kv4.x); kv4.y = to_tf32(kv4.y);
            kv4.z = to_tf32(kv4.z); kv4.w = to_tf32(kv4.w);
            *(float4*)&Ks[row * KST + c4 * 4] = kv4;
            float4 vv4 = *(const float4*)&Vb[(size_t)(kv0 + row) * D_ + c4 * 4];
            vv4.x = to_tf32(vv4.x); vv4.y = to_tf32(vv4.y);
            vv4.z = to_tf32(vv4.z); vv4.w = to_tf32(vv4.w);
            *(float4*)&Vs[row * VST + c4 * 4] = vv4;
        }
        if (tid < 64)
            madd[tid] = mask[b * S_ + kv0 + tid] ? 0.f : -1e9f;
        __syncthreads();

        // ---- S = Q K^T : [32 q x 64 kv] per warp, K(dh)=64 -------------
        float s[2][8][4];
        #pragma unroll
        for (int mi = 0; mi < 2; mi++)
            #pragma unroll
            for (int nt = 0; nt < 8; nt++)
                #pragma unroll
                for (int r = 0; r < 4; r++) s[mi][nt][r] = 0.f;

        #pragma unroll
        for (int kt = 0; kt < 8; kt++) {
            float a[2][4];
            #pragma unroll
            for (int mi = 0; mi < 2; mi++) {
                const int rl = w * 32 + mi * 16 + grp;
                a[mi][0] = Qs[rl * QST + kt * 8 + qd];
                a[mi][1] = Qs[(rl + 8) * QST + kt * 8 + qd];
                a[mi][2] = Qs[rl * QST + kt * 8 + qd + 4];
                a[mi][3] = Qs[(rl + 8) * QST + kt * 8 + qd + 4];
            }
            #pragma unroll
            for (int nt = 0; nt < 8; nt++) {
                float bk[2];
                bk[0] = Ks[(nt * 8 + grp) * KST + kt * 8 + qd];
                bk[1] = Ks[(nt * 8 + grp) * KST + kt * 8 + qd + 4];
                mma_tf32(s[0][nt], a[0], bk);
                mma_tf32(s[1][nt], a[1], bk);
            }
        }

        // ---- online softmax on C fragments ------------------------------
        #pragma unroll
        for (int mi = 0; mi < 2; mi++) {
            float mx0 = -1e30f, mx1 = -1e30f;
            #pragma unroll
            for (int nt = 0; nt < 8; nt++) {
                float2 ma = *(float2*)&madd[nt * 8 + 2 * qd];
                s[mi][nt][0] = fmaf(s[mi][nt][0], scale, ma.x);
                s[mi][nt][1] = fmaf(s[mi][nt][1], scale, ma.y);
                s[mi][nt][2] = fmaf(s[mi][nt][2], scale, ma.x);
                s[mi][nt][3] = fmaf(s[mi][nt][3], scale, ma.y);
                mx0 = fmaxf(mx0, fmaxf(s[mi][nt][0], s[mi][nt][1]));
                mx1 = fmaxf(mx1, fmaxf(s[mi][nt][2], s[mi][nt][3]));
            }
            mx0 = fmaxf(mx0, __shfl_xor_sync(0xffffffffu, mx0, 1));
            mx0 = fmaxf(mx0, __shfl_xor_sync(0xffffffffu, mx0, 2));
            mx1 = fmaxf(mx1, __shfl_xor_sync(0xffffffffu, mx1, 1));
            mx1 = fmaxf(mx1, __shfl_xor_sync(0xffffffffu, mx1, 2));
            const float mn0 = fmaxf(m_i[mi][0], mx0);
            const float mn1 = fmaxf(m_i[mi][1], mx1);
            const float al0 = __expf(m_i[mi][0] - mn0);
            const float al1 = __expf(m_i[mi][1] - mn1);
            float rs0 = 0.f, rs1 = 0.f;
            const int rl = w * 32 + mi * 16 + grp;
            #pragma unroll
            for (int nt = 0; nt < 8; nt++) {
                float p0 = __expf(s[mi][nt][0] - mn0);
                float p1 = __expf(s[mi][nt][1] - mn0);
                float p2 = __expf(s[mi][nt][2] - mn1);
                float p3 = __expf(s[mi][nt][3] - mn1);
                rs0 += p0 + p1;
                rs1 += p2 + p3;
                *(float2*)&Ps[rl * PST + nt * 8 + 2 * qd] =
                    make_float2(to_tf32(p0), to_tf32(p1));
                *(float2*)&Ps[(rl + 8) * PST + nt * 8 + 2 * qd] =
                    make_float2(to_tf32(p2), to_tf32(p3));
            }
            rs0 += __shfl_xor_sync(0xffffffffu, rs0, 1);
            rs0 += __shfl_xor_sync(0xffffffffu, rs0, 2);
            rs1 += __shfl_xor_sync(0xffffffffu, rs1, 1);
            rs1 += __shfl_xor_sync(0xffffffffu, rs1, 2);
            l_i[mi][0] = l_i[mi][0] * al0 + rs0;
            l_i[mi][1] = l_i[mi][1] * al1 + rs1;
            m_i[mi][0] = mn0;
            m_i[mi][1] = mn1;
            #pragma unroll
            for (int nt = 0; nt < 8; nt++) {
                o[mi][nt][0] *= al0;
                o[mi][nt][1] *= al0;
                o[mi][nt][2] *= al1;
                o[mi][nt][3] *= al1;
            }
        }
        __syncwarp();   // P rows are warp-private: warp-scope visibility only

        // ---- O += P V : [32 q x 64 dh] per warp, K(kv)=64 ---------------
        #pragma unroll
        for (int kt = 0; kt < 8; kt++) {
            float a[2][4];
            #pragma unroll
            for (int mi = 0; mi < 2; mi++) {
                const int rl = w * 32 + mi * 16 + grp;
                a[mi][0] = Ps[rl * PST + kt * 8 + qd];
                a[mi][1] = Ps[(rl + 8) * PST + kt * 8 + qd];
                a[mi][2] = Ps[rl * PST + kt * 8 + qd + 4];
                a[mi][3] = Ps[(rl + 8) * PST + kt * 8 + qd + 4];
            }
            #pragma unroll
            for (int nt = 0; nt < 8; nt++) {
                float bv[2];
                bv[0] = Vs[(kt * 8 + qd) * VST + nt * 8 + grp];
                bv[1] = Vs[(kt * 8 + qd + 4) * VST + nt * 8 + grp];
                mma_tf32(o[0][nt], a[0], bv);
                mma_tf32(o[1][nt], a[1], bv);
            }
        }
    }

    // ---- normalize + write out[b, q, h*64 + dh] -------------------------
    #pragma unroll
    for (int mi = 0; mi < 2; mi++) {
        const float inv0 = 1.f / l_i[mi][0];
        const float inv1 = 1.f / l_i[mi][1];
        const int rl = q0 + w * 32 + mi * 16 + grp;
        #pragma unroll
        for (int nt = 0; nt < 8; nt++) {
            const int col = h * DH_ + nt * 8 + 2 * qd;
            *(float2*)&out[((size_t)b * S_ + rl) * D_ + col] =
                make_float2(o[mi][nt][0] * inv0, o[mi][nt][1] * inv0);
            *(float2*)&out[((size_t)b * S_ + rl + 8) * D_ + col] =
                make_float2(o[mi][nt][2] * inv1, o[mi][nt][3] * inv1);
        }
    }
}

// ---------------------------------------------------------------------------
extern "C" void kernel_launch(void* const* d_in, const int* in_sizes, int n_in,
                              void* d_out, int out_size)
{
    const float* q    = (const float*)d_in[0];
    const float* k    = (const float*)d_in[1];
    const float* v    = (const float*)d_in[2];
    const int*   mask = (const int*)  d_in[3];
    const float* Wq   = (const float*)d_in[4];
    const float* bq   = (const float*)d_in[5];
    const float* Wk   = (const float*)d_in[6];
    const float* bk   = (const float*)d_in[7];
    const float* Wv   = (const float*)d_in[8];
    const float* bv   = (const float*)d_in[9];
    float* out = (float*)d_out;

    (void)in_sizes; (void)n_in; (void)out_size;

    cudaFuncSetAttribute(proj_mma,
                         cudaFuncAttributeMaxDynamicSharedMemorySize, PSMEM_TOT);
    dim3 g1(D_/128, M_/128, 3);
    proj_mma<<<g1, 256, PSMEM_TOT>>>(q, k, v, Wq, Wk, Wv, bq, bk, bv);

    cudaFuncSetAttribute(flash_attn_mma,
                         cudaFuncAttributeMaxDynamicSharedMemorySize,
                         FA_SMEM_BYTES);
    dim3 g2(S_/128, B_*H_);
    flash_attn_mma<<<g2, 128, FA_SMEM_BYTES>>>(mask, out);
}